// round 8
// baseline (speedup 1.0000x reference)
#include <cuda_runtime.h>
#include <cstdint>

// ---------------- problem constants ----------------
#define NN   65536      // base nodes
#define MM   65536      // local nodes
#define HH   128        // hidden / feature dim
#define BB   64         // groups
#define OUTD 2
#define ALPHA 0.9f
#define EMAX (1 << 20)  // 1M edges per graph (dataset-fixed)

// ---------------- device scratch (no runtime allocation allowed) ----------------
__device__ float g_base_x0[(size_t)NN * HH];
__device__ float g_base_x1[(size_t)NN * HH];
__device__ float g_local_x0[(size_t)MM * HH];
__device__ float g_local_x1[(size_t)MM * HH];
__device__ float g_sub[BB * HH];
__device__ float g_cnt[BB];

// CSR scratch (base graph [0], local graph [1])
__device__ int   g_csr_cnt [2][NN];
__device__ int   g_csr_ptr [2][NN + 1];
__device__ int   g_csr_fill[2][NN];
__device__ int   g_csr_src [2][EMAX];
__device__ float g_csr_w   [2][EMAX];
__device__ int   g_chunks  [2][256];

// ---------------- fused (SpMM?) + GEMM + bias + relu ----------------
// C[64x128 tile] = relu(A' @ W + bias)
//   AGG=false: A' rows read directly from X (input projections)
//   AGG=true : A' row r = sum_{e in CSR row} cw[e] * X[csrc[e]]   (fused SpMM)
//   MIX=true : A' = ALPHA*A' + (1-ALPHA)*BX[c2o[row]]             (local layers)
// 256 threads, 4x8 microtile, FFMA2 math, 96KB smem -> 2 CTAs/SM.
#define GEMM_SMEM ((128 * 64 + 128 * 128) * sizeof(float))   // 98304 B

__device__ __forceinline__ void ffma2(unsigned long long& d,
                                      unsigned long long a,
                                      unsigned long long b)
{
    asm("fma.rn.f32x2 %0, %1, %2, %0;" : "+l"(d) : "l"(a), "l"(b));
}

__device__ __forceinline__ unsigned long long dup_reg(float x)
{
    unsigned long long r;
    asm("mov.b64 %0, {%1, %1};" : "=l"(r) : "r"(__float_as_uint(x)));
    return r;
}

template<bool AGG, bool MIX>
__global__ void __launch_bounds__(256, 2)
gemm_fused(const float* __restrict__ X,
           const int* __restrict__ ptr,
           const int* __restrict__ csrc,
           const float* __restrict__ cw,
           const float* __restrict__ W,
           const float* __restrict__ bias,
           float* __restrict__ C,
           const float* __restrict__ BX,
           const int* __restrict__ c2o)
{
    extern __shared__ float smem[];
    float* As = smem;                // [128][64]   As[k][r ^ swz(k)]
    float* Ws = smem + 128 * 64;     // [128][128]  Ws[k][col]

    const int tid  = threadIdx.x;
    const int row0 = blockIdx.x * 64;
    const int lane = tid & 31;
    const int w    = tid >> 5;

    // ---- stage W (16384 floats), coalesced ----
    {
        const float4* W4  = (const float4*)W;
        float4*       Ws4 = (float4*)Ws;
        #pragma unroll
        for (int i = 0; i < 16; i++) Ws4[tid + 256 * i] = W4[tid + 256 * i];
    }

    // ---- stage A' tile: 8 rows per warp, lane owns k = 4*lane..4*lane+3 ----
    #pragma unroll 1
    for (int i = 0; i < 8; i++) {
        const int r    = w + 8 * i;          // 0..63
        const int grow = row0 + r;
        float4 acc;
        if (AGG) {
            // fused SpMM: gather-accumulate this CSR row
            const int beg = __ldg(&ptr[grow]);
            const int end = __ldg(&ptr[grow + 1]);
            float4 a0 = make_float4(0.f, 0.f, 0.f, 0.f);
            float4 a1 = make_float4(0.f, 0.f, 0.f, 0.f);
            int e = beg;
            for (; e + 1 < end; e += 2) {
                int   s0 = csrc[e];     float w0 = cw[e];
                int   s1 = csrc[e + 1]; float w1 = cw[e + 1];
                float4 v0 = *(const float4*)&X[(size_t)s0 * HH + lane * 4];
                float4 v1 = *(const float4*)&X[(size_t)s1 * HH + lane * 4];
                a0.x = fmaf(w0, v0.x, a0.x); a0.y = fmaf(w0, v0.y, a0.y);
                a0.z = fmaf(w0, v0.z, a0.z); a0.w = fmaf(w0, v0.w, a0.w);
                a1.x = fmaf(w1, v1.x, a1.x); a1.y = fmaf(w1, v1.y, a1.y);
                a1.z = fmaf(w1, v1.z, a1.z); a1.w = fmaf(w1, v1.w, a1.w);
            }
            if (e < end) {
                int s = csrc[e]; float wt = cw[e];
                float4 v = *(const float4*)&X[(size_t)s * HH + lane * 4];
                a0.x = fmaf(wt, v.x, a0.x); a0.y = fmaf(wt, v.y, a0.y);
                a0.z = fmaf(wt, v.z, a0.z); a0.w = fmaf(wt, v.w, a0.w);
            }
            acc = make_float4(a0.x + a1.x, a0.y + a1.y, a0.z + a1.z, a0.w + a1.w);
        } else {
            acc = *(const float4*)&X[(size_t)grow * HH + lane * 4];
        }
        if (MIX) {
            int o = __ldg(&c2o[grow]);
            float4 b = *(const float4*)&BX[(size_t)o * HH + lane * 4];
            acc.x = ALPHA * acc.x + (1.0f - ALPHA) * b.x;
            acc.y = ALPHA * acc.y + (1.0f - ALPHA) * b.y;
            acc.z = ALPHA * acc.z + (1.0f - ALPHA) * b.z;
            acc.w = ALPHA * acc.w + (1.0f - ALPHA) * b.w;
        }
        const int rs = r ^ (4 * (lane & 15));      // swz(k) for k = 4*lane+q
        As[(4 * lane + 0) * 64 + rs] = acc.x;
        As[(4 * lane + 1) * 64 + rs] = acc.y;
        As[(4 * lane + 2) * 64 + rs] = acc.z;
        As[(4 * lane + 3) * 64 + rs] = acc.w;
    }
    __syncthreads();

    const int j  = tid & 15;          // column group
    const int tr = (tid >> 4) * 4;    // row offset (0..60)
    const int c0 = 4 * j;
    const int c1 = 64 + 4 * j;

    unsigned long long acc2[4][4];
    #pragma unroll
    for (int m = 0; m < 4; m++)
        #pragma unroll
        for (int p = 0; p < 4; p++) acc2[m][p] = 0ull;

    #pragma unroll 4
    for (int k = 0; k < 128; k++) {
        const int ab = tr ^ (4 * ((k >> 2) & 15));
        float4 a0 = *(const float4*)&As[k * 64 + ab];
        ulonglong2 w0 = *(const ulonglong2*)&Ws[k * 128 + c0];
        ulonglong2 w1 = *(const ulonglong2*)&Ws[k * 128 + c1];

        unsigned long long a2[4];
        a2[0] = dup_reg(a0.x); a2[1] = dup_reg(a0.y);
        a2[2] = dup_reg(a0.z); a2[3] = dup_reg(a0.w);
        unsigned long long wv[4] = {w0.x, w0.y, w1.x, w1.y};

        #pragma unroll
        for (int m = 0; m < 4; m++)
            #pragma unroll
            for (int p = 0; p < 4; p++)
                ffma2(acc2[m][p], a2[m], wv[p]);
    }

    float4 bv0 = *(const float4*)&bias[c0];
    float4 bv1 = *(const float4*)&bias[c1];

    #pragma unroll
    for (int m = 0; m < 4; m++) {
        float2 p0 = *(float2*)&acc2[m][0];
        float2 p1 = *(float2*)&acc2[m][1];
        float2 p2 = *(float2*)&acc2[m][2];
        float2 p3 = *(float2*)&acc2[m][3];
        float4 o0, o1;
        o0.x = fmaxf(p0.x + bv0.x, 0.f);
        o0.y = fmaxf(p0.y + bv0.y, 0.f);
        o0.z = fmaxf(p1.x + bv0.z, 0.f);
        o0.w = fmaxf(p1.y + bv0.w, 0.f);
        o1.x = fmaxf(p2.x + bv1.x, 0.f);
        o1.y = fmaxf(p2.y + bv1.y, 0.f);
        o1.z = fmaxf(p3.x + bv1.z, 0.f);
        o1.w = fmaxf(p3.y + bv1.w, 0.f);
        float* cp = &C[(size_t)(row0 + tr + m) * HH];
        *(float4*)&cp[c0] = o0;
        *(float4*)&cp[c1] = o1;
    }
}

// ---------------- CSR build ----------------
__global__ void hist_kernel(const int* __restrict__ dst, int* __restrict__ cnt, int E)
{
    int e = blockIdx.x * blockDim.x + threadIdx.x;
    if (e < E) atomicAdd(&cnt[dst[e]], 1);
}

__global__ void chunksum_kernel(const int* __restrict__ cnt, int* __restrict__ chunks)
{
    const int tid  = threadIdx.x;
    const int lane = tid & 31;
    const int w    = tid >> 5;
    __shared__ int wsum[8];
    int v = cnt[blockIdx.x * 256 + tid];
    #pragma unroll
    for (int off = 16; off > 0; off >>= 1)
        v += __shfl_down_sync(0xffffffffu, v, off);
    if (lane == 0) wsum[w] = v;
    __syncthreads();
    if (tid == 0) {
        int s = 0;
        #pragma unroll
        for (int i = 0; i < 8; i++) s += wsum[i];
        chunks[blockIdx.x] = s;
    }
}

__global__ void scan_chunks_kernel(int* __restrict__ chunks, int* __restrict__ ptr, int n)
{
    const int tid  = threadIdx.x;
    const int lane = tid & 31;
    const int w    = tid >> 5;
    __shared__ int wsum[8];
    int v = chunks[tid];
    int inc = v;
    #pragma unroll
    for (int off = 1; off < 32; off <<= 1) {
        int t = __shfl_up_sync(0xffffffffu, inc, off);
        if (lane >= off) inc += t;
    }
    if (lane == 31) wsum[w] = inc;
    __syncthreads();
    if (w == 0 && lane < 8) {
        int s = wsum[lane];
        #pragma unroll
        for (int off = 1; off < 8; off <<= 1) {
            int t = __shfl_up_sync(0x000000ffu, s, off);
            if (lane >= off) s += t;
        }
        wsum[lane] = s;
    }
    __syncthreads();
    int excl = inc - v + (w > 0 ? wsum[w - 1] : 0);
    chunks[tid] = excl;
    if (tid == 255) ptr[n] = excl + v;
}

__global__ void write_ptr_kernel(const int* __restrict__ cnt,
                                 const int* __restrict__ chunks,
                                 int* __restrict__ ptr)
{
    const int tid  = threadIdx.x;
    const int lane = tid & 31;
    const int w    = tid >> 5;
    __shared__ int wsum[8];
    const int gid = blockIdx.x * 256 + tid;
    int v = cnt[gid];
    int inc = v;
    #pragma unroll
    for (int off = 1; off < 32; off <<= 1) {
        int t = __shfl_up_sync(0xffffffffu, inc, off);
        if (lane >= off) inc += t;
    }
    if (lane == 31) wsum[w] = inc;
    __syncthreads();
    if (w == 0 && lane < 8) {
        int s = wsum[lane];
        #pragma unroll
        for (int off = 1; off < 8; off <<= 1) {
            int t = __shfl_up_sync(0x000000ffu, s, off);
            if (lane >= off) s += t;
        }
        wsum[lane] = s;
    }
    __syncthreads();
    ptr[gid] = inc - v + (w > 0 ? wsum[w - 1] : 0) + chunks[blockIdx.x];
}

__global__ void scatter_kernel(const int* __restrict__ src,
                               const int* __restrict__ dst,
                               const float* __restrict__ w,
                               const int* __restrict__ ptr,
                               int* __restrict__ fill,
                               int* __restrict__ csrc,
                               float* __restrict__ cw, int E)
{
    int e = blockIdx.x * blockDim.x + threadIdx.x;
    if (e >= E) return;
    int d = dst[e];
    int pos = ptr[d] + atomicAdd(&fill[d], 1);
    csrc[pos] = src[e];
    cw[pos]   = w[e];
}

// ---------------- pooling: two-stage segment-sum into g_sub / g_cnt ----------------
__global__ void pool_kernel(const float* __restrict__ lx,
                            const int* __restrict__ midx,
                            const int* __restrict__ mgid,
                            float* __restrict__ gsub,
                            float* __restrict__ gcnt,
                            int K, int entries_per_block)
{
    __shared__ float acc[BB * HH];   // 32 KB
    __shared__ float cnt[BB];
    const int tid = threadIdx.x;
    for (int i = tid; i < BB * HH; i += blockDim.x) acc[i] = 0.f;
    if (tid < BB) cnt[tid] = 0.f;
    __syncthreads();

    const int warp = tid >> 5;
    const int lane = tid & 31;
    const int base = blockIdx.x * entries_per_block;
    const int end  = min(base + entries_per_block, K);
    for (int k = base + warp; k < end; k += (int)(blockDim.x >> 5)) {
        int idx = midx[k];
        int g   = mgid[k];
        float4 v = *(const float4*)&lx[(size_t)idx * HH + lane * 4];
        atomicAdd(&acc[g * HH + lane * 4 + 0], v.x);
        atomicAdd(&acc[g * HH + lane * 4 + 1], v.y);
        atomicAdd(&acc[g * HH + lane * 4 + 2], v.z);
        atomicAdd(&acc[g * HH + lane * 4 + 3], v.w);
        if (lane == 0) atomicAdd(&cnt[g], 1.f);
    }
    __syncthreads();

    for (int i = tid; i < BB * HH; i += blockDim.x)
        if (acc[i] != 0.f) atomicAdd(&gsub[i], acc[i]);
    if (tid < BB && cnt[tid] != 0.f) atomicAdd(&gcnt[tid], cnt[tid]);
}

// ---------------- final: out[b][o] = (sub[b]/max(cnt,1)) @ Wp + bp ----------------
__global__ void final_kernel(const float* __restrict__ gsub,
                             const float* __restrict__ gcnt,
                             const float* __restrict__ Wp,
                             const float* __restrict__ bp,
                             float* __restrict__ out)
{
    int t = threadIdx.x;                 // 0..127
    if (t >= BB * OUTD) return;
    int b = t >> 1, o = t & 1;
    float c = fmaxf(gcnt[b], 1.f);
    float s = 0.f;
    #pragma unroll 8
    for (int h = 0; h < HH; h++) s = fmaf(gsub[b * HH + h], Wp[h * OUTD + o], s);
    out[t] = s / c + bp[o];
}

// ---------------- host orchestration ----------------
extern "C" void kernel_launch(void* const* d_in, const int* in_sizes, int n_in,
                              void* d_out, int out_size)
{
    const float* x    = (const float*)d_in[0];
    const int*   ei   = (const int*)  d_in[1];
    const float* ew   = (const float*)d_in[2];
    const float* lx0  = (const float*)d_in[3];
    const int*   c2o  = (const int*)  d_in[4];
    const int*   lei  = (const int*)  d_in[5];
    const float* lev  = (const float*)d_in[6];
    const int*   midx = (const int*)  d_in[7];
    const int*   mgid = (const int*)  d_in[8];
    // d_in[9] = B (scalar) -- fixed at 64
    const float* Wb    = (const float*)d_in[10];
    const float* bb    = (const float*)d_in[11];
    const float* Wl    = (const float*)d_in[12];
    const float* bl    = (const float*)d_in[13];
    const float* Wbase = (const float*)d_in[14];
    const float* bbase = (const float*)d_in[15];
    const float* Wloc  = (const float*)d_in[16];
    const float* bloc  = (const float*)d_in[17];
    const float* Wp    = (const float*)d_in[18];
    const float* bp    = (const float*)d_in[19];
    float* out = (float*)d_out;

    const int N  = in_sizes[0] / HH;
    const int M  = in_sizes[3] / HH;
    const int E  = in_sizes[1] / 2;
    const int EL = in_sizes[5] / 2;
    const int K  = in_sizes[7];
    const int L  = in_sizes[14] / (HH * HH);

    float *bx0, *bx1, *lxA, *lxB, *sub, *cntp;
    cudaGetSymbolAddress((void**)&bx0,  g_base_x0);
    cudaGetSymbolAddress((void**)&bx1,  g_base_x1);
    cudaGetSymbolAddress((void**)&lxA,  g_local_x0);
    cudaGetSymbolAddress((void**)&lxB,  g_local_x1);
    cudaGetSymbolAddress((void**)&sub,  g_sub);
    cudaGetSymbolAddress((void**)&cntp, g_cnt);

    int *csr_cnt, *csr_ptr, *csr_fill, *csr_src, *chunks;
    float* csr_w;
    cudaGetSymbolAddress((void**)&csr_cnt,  g_csr_cnt);
    cudaGetSymbolAddress((void**)&csr_ptr,  g_csr_ptr);
    cudaGetSymbolAddress((void**)&csr_fill, g_csr_fill);
    cudaGetSymbolAddress((void**)&csr_src,  g_csr_src);
    cudaGetSymbolAddress((void**)&csr_w,    g_csr_w);
    cudaGetSymbolAddress((void**)&chunks,   g_chunks);

    int*   cnt_b  = csr_cnt;            int*   cnt_l  = csr_cnt + NN;
    int*   ptr_b  = csr_ptr;            int*   ptr_l  = csr_ptr + (NN + 1);
    int*   fill_b = csr_fill;           int*   fill_l = csr_fill + NN;
    int*   src_b  = csr_src;            int*   src_l  = csr_src + EMAX;
    float* w_b    = csr_w;              float* w_l    = csr_w + EMAX;
    int*   chk_b  = chunks;             int*   chk_l  = chunks + 256;

    cudaFuncSetAttribute(gemm_fused<false, false>,
                         cudaFuncAttributeMaxDynamicSharedMemorySize, (int)GEMM_SMEM);
    cudaFuncSetAttribute(gemm_fused<true, false>,
                         cudaFuncAttributeMaxDynamicSharedMemorySize, (int)GEMM_SMEM);
    cudaFuncSetAttribute(gemm_fused<true, true>,
                         cudaFuncAttributeMaxDynamicSharedMemorySize, (int)GEMM_SMEM);

    // ---------- CSR build (once per graph, reused across layers) ----------
    cudaMemsetAsync(csr_cnt,  0, 2 * NN * sizeof(int));
    cudaMemsetAsync(csr_fill, 0, 2 * NN * sizeof(int));
    const int eb = (E  + 255) / 256;
    const int el = (EL + 255) / 256;
    hist_kernel<<<eb, 256>>>(ei  + E,  cnt_b, E);
    hist_kernel<<<el, 256>>>(lei + EL, cnt_l, EL);
    chunksum_kernel<<<256, 256>>>(cnt_b, chk_b);
    chunksum_kernel<<<256, 256>>>(cnt_l, chk_l);
    scan_chunks_kernel<<<1, 256>>>(chk_b, ptr_b, N);
    scan_chunks_kernel<<<1, 256>>>(chk_l, ptr_l, M);
    write_ptr_kernel<<<256, 256>>>(cnt_b, chk_b, ptr_b);
    write_ptr_kernel<<<256, 256>>>(cnt_l, chk_l, ptr_l);
    scatter_kernel<<<eb, 256>>>(ei,  ei  + E,  ew,  ptr_b, fill_b, src_b, w_b, E);
    scatter_kernel<<<el, 256>>>(lei, lei + EL, lev, ptr_l, fill_l, src_l, w_l, EL);

    // ---------- input projections (direct staging) ----------
    const int gb_N = N / 64;
    const int gb_M = M / 64;
    gemm_fused<false, false><<<gb_N, 256, GEMM_SMEM>>>(
        x,   nullptr, nullptr, nullptr, Wb, bb, bx0, nullptr, nullptr);
    gemm_fused<false, false><<<gb_M, 256, GEMM_SMEM>>>(
        lx0, nullptr, nullptr, nullptr, Wl, bl, lxA, nullptr, nullptr);

    // ---------- layers: fused SpMM+GEMM, ping-pong buffers ----------
    float* b_cur = bx0; float* b_nxt = bx1;
    float* l_cur = lxA; float* l_nxt = lxB;
    for (int l = 0; l < L; l++) {
        // base: b_nxt = relu(spmm(b_cur) @ Wbase_l + b)
        gemm_fused<true, false><<<gb_N, 256, GEMM_SMEM>>>(
            b_cur, ptr_b, src_b, w_b,
            Wbase + (size_t)l * HH * HH, bbase + (size_t)l * HH, b_nxt,
            nullptr, nullptr);
        // local: l_nxt = relu((ALPHA*spmm(l_cur) + (1-ALPHA)*b_nxt[c2o]) @ Wloc_l + b)
        gemm_fused<true, true><<<gb_M, 256, GEMM_SMEM>>>(
            l_cur, ptr_l, src_l, w_l,
            Wloc + (size_t)l * HH * HH, bloc + (size_t)l * HH, l_nxt,
            b_nxt, c2o);
        float* t;
        t = b_cur; b_cur = b_nxt; b_nxt = t;
        t = l_cur; l_cur = l_nxt; l_nxt = t;
    }

    // ---------- scatter-mean pooling + final projection ----------
    cudaMemsetAsync(sub,  0, BB * HH * sizeof(float));
    cudaMemsetAsync(cntp, 0, BB * sizeof(float));
    const int pool_blocks = 128;
    const int entries_per_block = (K + pool_blocks - 1) / pool_blocks;
    pool_kernel<<<pool_blocks, 256>>>(l_cur, midx, mgid, sub, cntp, K, entries_per_block);
    final_kernel<<<1, 128>>>(sub, cntp, Wp, bp, out);
}

// round 9
// speedup vs baseline: 1.1795x; 1.1795x over previous
#include <cuda_runtime.h>
#include <cstdint>

// ---------------- problem constants ----------------
#define NN   65536      // base nodes
#define MM   65536      // local nodes
#define HH   128        // hidden / feature dim
#define BB   64         // groups
#define OUTD 2
#define ALPHA 0.9f
#define EMAX (1 << 20)  // 1M edges per graph (dataset-fixed)

// ---------------- device scratch (no runtime allocation allowed) ----------------
__device__ float g_base_x0 [(size_t)NN * HH];
__device__ float g_base_x1 [(size_t)NN * HH];
__device__ float g_base_agg[(size_t)NN * HH];
__device__ float g_local_x0[(size_t)MM * HH];
__device__ float g_local_x1[(size_t)MM * HH];
__device__ float g_local_agg[(size_t)MM * HH];
__device__ float g_sub[BB * HH];
__device__ float g_cnt[BB];

// CSR scratch (base graph [0], local graph [1])
__device__ int   g_csr_cnt [2][NN];
__device__ int   g_csr_ptr [2][NN + 1];
__device__ int   g_csr_fill[2][NN];
__device__ int   g_csr_src [2][EMAX];
__device__ float g_csr_w   [2][EMAX];
__device__ int   g_chunks  [2][256];

// ---------------- GEMM: C[R x128] = relu(A'[R x128] @ W[128x128] + bias) ----------------
// (round-7 WIN version: 64x128 tile, 256 thr, 4x8 microtile, FFMA2, 96KB smem, 2 CTA/SM)
#define GEMM_SMEM ((128 * 64 + 128 * 128) * sizeof(float))   // 98304 B

__device__ __forceinline__ void ffma2(unsigned long long& d,
                                      unsigned long long a,
                                      unsigned long long b)
{
    asm("fma.rn.f32x2 %0, %1, %2, %0;" : "+l"(d) : "l"(a), "l"(b));
}

__device__ __forceinline__ unsigned long long dup_reg(float x)
{
    unsigned long long r;
    asm("mov.b64 %0, {%1, %1};" : "=l"(r) : "r"(__float_as_uint(x)));
    return r;
}

template<bool MIX>
__global__ void __launch_bounds__(256, 2)
gemm128_bias_relu(const float* __restrict__ A,
                  const float* __restrict__ W,
                  const float* __restrict__ bias,
                  float* __restrict__ C,
                  const float* __restrict__ BX,
                  const int* __restrict__ c2o)
{
    extern __shared__ float smem[];
    float* As = smem;                // [128][64]   As[k][r ^ swz(k)]
    float* Ws = smem + 128 * 64;     // [128][128]  Ws[k][col]

    const int tid  = threadIdx.x;
    const int row0 = blockIdx.x * 64;

    {
        const float4* W4  = (const float4*)W;
        float4*       Ws4 = (float4*)Ws;
        #pragma unroll
        for (int i = 0; i < 16; i++) Ws4[tid + 256 * i] = W4[tid + 256 * i];
    }
    {
        const float4* A4 = (const float4*)(A + (size_t)row0 * HH);
        #pragma unroll
        for (int i = 0; i < 8; i++) {
            int idx = tid + 256 * i;      // = r*32 + k4
            int r   = idx >> 5;           // 0..63
            int k4  = idx & 31;
            float4 v = A4[idx];
            if (MIX) {
                int o = __ldg(&c2o[row0 + r]);
                float4 b = *(const float4*)&BX[(size_t)o * HH + k4 * 4];
                v.x = ALPHA * v.x + (1.0f - ALPHA) * b.x;
                v.y = ALPHA * v.y + (1.0f - ALPHA) * b.y;
                v.z = ALPHA * v.z + (1.0f - ALPHA) * b.z;
                v.w = ALPHA * v.w + (1.0f - ALPHA) * b.w;
            }
            int rs = r ^ (4 * (k4 & 15));
            As[(4 * k4 + 0) * 64 + rs] = v.x;
            As[(4 * k4 + 1) * 64 + rs] = v.y;
            As[(4 * k4 + 2) * 64 + rs] = v.z;
            As[(4 * k4 + 3) * 64 + rs] = v.w;
        }
    }
    __syncthreads();

    const int j  = tid & 15;
    const int tr = (tid >> 4) * 4;
    const int c0 = 4 * j;
    const int c1 = 64 + 4 * j;

    unsigned long long acc2[4][4];
    #pragma unroll
    for (int m = 0; m < 4; m++)
        #pragma unroll
        for (int p = 0; p < 4; p++) acc2[m][p] = 0ull;

    #pragma unroll 4
    for (int k = 0; k < 128; k++) {
        const int ab = tr ^ (4 * ((k >> 2) & 15));
        float4 a0 = *(const float4*)&As[k * 64 + ab];
        ulonglong2 w0 = *(const ulonglong2*)&Ws[k * 128 + c0];
        ulonglong2 w1 = *(const ulonglong2*)&Ws[k * 128 + c1];

        unsigned long long a2[4];
        a2[0] = dup_reg(a0.x); a2[1] = dup_reg(a0.y);
        a2[2] = dup_reg(a0.z); a2[3] = dup_reg(a0.w);
        unsigned long long wv[4] = {w0.x, w0.y, w1.x, w1.y};

        #pragma unroll
        for (int m = 0; m < 4; m++)
            #pragma unroll
            for (int p = 0; p < 4; p++)
                ffma2(acc2[m][p], a2[m], wv[p]);
    }

    float4 bv0 = *(const float4*)&bias[c0];
    float4 bv1 = *(const float4*)&bias[c1];

    #pragma unroll
    for (int m = 0; m < 4; m++) {
        float2 p0 = *(float2*)&acc2[m][0];
        float2 p1 = *(float2*)&acc2[m][1];
        float2 p2 = *(float2*)&acc2[m][2];
        float2 p3 = *(float2*)&acc2[m][3];
        float4 o0, o1;
        o0.x = fmaxf(p0.x + bv0.x, 0.f);
        o0.y = fmaxf(p0.y + bv0.y, 0.f);
        o0.z = fmaxf(p1.x + bv0.z, 0.f);
        o0.w = fmaxf(p1.y + bv0.w, 0.f);
        o1.x = fmaxf(p2.x + bv1.x, 0.f);
        o1.y = fmaxf(p2.y + bv1.y, 0.f);
        o1.z = fmaxf(p3.x + bv1.z, 0.f);
        o1.w = fmaxf(p3.y + bv1.w, 0.f);
        float* cp = &C[(size_t)(row0 + tr + m) * HH];
        *(float4*)&cp[c0] = o0;
        *(float4*)&cp[c1] = o1;
    }
}

// ---------------- CSR build ----------------
__global__ void hist_kernel(const int* __restrict__ dst, int* __restrict__ cnt, int E)
{
    int e = blockIdx.x * blockDim.x + threadIdx.x;
    if (e < E) atomicAdd(&cnt[dst[e]], 1);
}

__global__ void chunksum_kernel(const int* __restrict__ cnt, int* __restrict__ chunks)
{
    const int tid  = threadIdx.x;
    const int lane = tid & 31;
    const int w    = tid >> 5;
    __shared__ int wsum[8];
    int v = cnt[blockIdx.x * 256 + tid];
    #pragma unroll
    for (int off = 16; off > 0; off >>= 1)
        v += __shfl_down_sync(0xffffffffu, v, off);
    if (lane == 0) wsum[w] = v;
    __syncthreads();
    if (tid == 0) {
        int s = 0;
        #pragma unroll
        for (int i = 0; i < 8; i++) s += wsum[i];
        chunks[blockIdx.x] = s;
    }
}

__global__ void scan_chunks_kernel(int* __restrict__ chunks, int* __restrict__ ptr, int n)
{
    const int tid  = threadIdx.x;
    const int lane = tid & 31;
    const int w    = tid >> 5;
    __shared__ int wsum[8];
    int v = chunks[tid];
    int inc = v;
    #pragma unroll
    for (int off = 1; off < 32; off <<= 1) {
        int t = __shfl_up_sync(0xffffffffu, inc, off);
        if (lane >= off) inc += t;
    }
    if (lane == 31) wsum[w] = inc;
    __syncthreads();
    if (w == 0 && lane < 8) {
        int s = wsum[lane];
        #pragma unroll
        for (int off = 1; off < 8; off <<= 1) {
            int t = __shfl_up_sync(0x000000ffu, s, off);
            if (lane >= off) s += t;
        }
        wsum[lane] = s;
    }
    __syncthreads();
    int excl = inc - v + (w > 0 ? wsum[w - 1] : 0);
    chunks[tid] = excl;
    if (tid == 255) ptr[n] = excl + v;
}

__global__ void write_ptr_kernel(const int* __restrict__ cnt,
                                 const int* __restrict__ chunks,
                                 int* __restrict__ ptr)
{
    const int tid  = threadIdx.x;
    const int lane = tid & 31;
    const int w    = tid >> 5;
    __shared__ int wsum[8];
    const int gid = blockIdx.x * 256 + tid;
    int v = cnt[gid];
    int inc = v;
    #pragma unroll
    for (int off = 1; off < 32; off <<= 1) {
        int t = __shfl_up_sync(0xffffffffu, inc, off);
        if (lane >= off) inc += t;
    }
    if (lane == 31) wsum[w] = inc;
    __syncthreads();
    if (w == 0 && lane < 8) {
        int s = wsum[lane];
        #pragma unroll
        for (int off = 1; off < 8; off <<= 1) {
            int t = __shfl_up_sync(0x000000ffu, s, off);
            if (lane >= off) s += t;
        }
        wsum[lane] = s;
    }
    __syncthreads();
    ptr[gid] = inc - v + (w > 0 ? wsum[w - 1] : 0) + chunks[blockIdx.x];
}

__global__ void scatter_kernel(const int* __restrict__ src,
                               const int* __restrict__ dst,
                               const float* __restrict__ w,
                               const int* __restrict__ ptr,
                               int* __restrict__ fill,
                               int* __restrict__ csrc,
                               float* __restrict__ cw, int E)
{
    int e = blockIdx.x * blockDim.x + threadIdx.x;
    if (e >= E) return;
    int d = dst[e];
    int pos = ptr[d] + atomicAdd(&fill[d], 1);
    csrc[pos] = src[e];
    cw[pos]   = w[e];
}

// ---------------- SpMM over CSR: one warp per destination row ----------------
__global__ void __launch_bounds__(256, 8)
spmm_csr(const float* __restrict__ X,
         const int* __restrict__ ptr,
         const int* __restrict__ csrc,
         const float* __restrict__ cw,
         float* __restrict__ Y, int n)
{
    const int lane = threadIdx.x & 31;
    const int row  = (blockIdx.x * blockDim.x + threadIdx.x) >> 5;
    if (row >= n) return;
    const int beg = ptr[row];
    const int end = ptr[row + 1];
    float4 acc0 = make_float4(0.f, 0.f, 0.f, 0.f);
    float4 acc1 = make_float4(0.f, 0.f, 0.f, 0.f);
    int i = beg;
    for (; i + 1 < end; i += 2) {
        int   s0 = csrc[i];     float w0 = cw[i];
        int   s1 = csrc[i + 1]; float w1 = cw[i + 1];
        float4 v0 = *(const float4*)&X[(size_t)s0 * HH + lane * 4];
        float4 v1 = *(const float4*)&X[(size_t)s1 * HH + lane * 4];
        acc0.x = fmaf(w0, v0.x, acc0.x); acc0.y = fmaf(w0, v0.y, acc0.y);
        acc0.z = fmaf(w0, v0.z, acc0.z); acc0.w = fmaf(w0, v0.w, acc0.w);
        acc1.x = fmaf(w1, v1.x, acc1.x); acc1.y = fmaf(w1, v1.y, acc1.y);
        acc1.z = fmaf(w1, v1.z, acc1.z); acc1.w = fmaf(w1, v1.w, acc1.w);
    }
    if (i < end) {
        int s = csrc[i]; float w = cw[i];
        float4 v = *(const float4*)&X[(size_t)s * HH + lane * 4];
        acc0.x = fmaf(w, v.x, acc0.x); acc0.y = fmaf(w, v.y, acc0.y);
        acc0.z = fmaf(w, v.z, acc0.z); acc0.w = fmaf(w, v.w, acc0.w);
    }
    acc0.x += acc1.x; acc0.y += acc1.y; acc0.z += acc1.z; acc0.w += acc1.w;
    *(float4*)&Y[(size_t)row * HH + lane * 4] = acc0;
}

// ---------------- pooling ----------------
__global__ void pool_kernel(const float* __restrict__ lx,
                            const int* __restrict__ midx,
                            const int* __restrict__ mgid,
                            float* __restrict__ gsub,
                            float* __restrict__ gcnt,
                            int K, int entries_per_block)
{
    __shared__ float acc[BB * HH];
    __shared__ float cnt[BB];
    const int tid = threadIdx.x;
    for (int i = tid; i < BB * HH; i += blockDim.x) acc[i] = 0.f;
    if (tid < BB) cnt[tid] = 0.f;
    __syncthreads();

    const int warp = tid >> 5;
    const int lane = tid & 31;
    const int base = blockIdx.x * entries_per_block;
    const int end  = min(base + entries_per_block, K);
    for (int k = base + warp; k < end; k += (int)(blockDim.x >> 5)) {
        int idx = midx[k];
        int g   = mgid[k];
        float4 v = *(const float4*)&lx[(size_t)idx * HH + lane * 4];
        atomicAdd(&acc[g * HH + lane * 4 + 0], v.x);
        atomicAdd(&acc[g * HH + lane * 4 + 1], v.y);
        atomicAdd(&acc[g * HH + lane * 4 + 2], v.z);
        atomicAdd(&acc[g * HH + lane * 4 + 3], v.w);
        if (lane == 0) atomicAdd(&cnt[g], 1.f);
    }
    __syncthreads();

    for (int i = tid; i < BB * HH; i += blockDim.x)
        if (acc[i] != 0.f) atomicAdd(&gsub[i], acc[i]);
    if (tid < BB && cnt[tid] != 0.f) atomicAdd(&gcnt[tid], cnt[tid]);
}

__global__ void final_kernel(const float* __restrict__ gsub,
                             const float* __restrict__ gcnt,
                             const float* __restrict__ Wp,
                             const float* __restrict__ bp,
                             float* __restrict__ out)
{
    int t = threadIdx.x;
    if (t >= BB * OUTD) return;
    int b = t >> 1, o = t & 1;
    float c = fmaxf(gcnt[b], 1.f);
    float s = 0.f;
    #pragma unroll 8
    for (int h = 0; h < HH; h++) s = fmaf(gsub[b * HH + h], Wp[h * OUTD + o], s);
    out[t] = s / c + bp[o];
}

// ---------------- persistent stream/event resources (created once, pre-capture) ----
static cudaStream_t g_s1 = nullptr;
static cudaEvent_t  g_ev[8];

// ---------------- host orchestration: two-stream fork/join ----------------
extern "C" void kernel_launch(void* const* d_in, const int* in_sizes, int n_in,
                              void* d_out, int out_size)
{
    const float* x    = (const float*)d_in[0];
    const int*   ei   = (const int*)  d_in[1];
    const float* ew   = (const float*)d_in[2];
    const float* lx0i = (const float*)d_in[3];
    const int*   c2o  = (const int*)  d_in[4];
    const int*   lei  = (const int*)  d_in[5];
    const float* lev  = (const float*)d_in[6];
    const int*   midx = (const int*)  d_in[7];
    const int*   mgid = (const int*)  d_in[8];
    const float* Wb    = (const float*)d_in[10];
    const float* bb    = (const float*)d_in[11];
    const float* Wl    = (const float*)d_in[12];
    const float* bl    = (const float*)d_in[13];
    const float* Wbase = (const float*)d_in[14];
    const float* bbase = (const float*)d_in[15];
    const float* Wloc  = (const float*)d_in[16];
    const float* bloc  = (const float*)d_in[17];
    const float* Wp    = (const float*)d_in[18];
    const float* bp    = (const float*)d_in[19];
    float* out = (float*)d_out;

    const int N  = in_sizes[0] / HH;
    const int M  = in_sizes[3] / HH;
    const int E  = in_sizes[1] / 2;
    const int EL = in_sizes[5] / 2;
    const int K  = in_sizes[7];
    const int L  = in_sizes[14] / (HH * HH);

    if (!g_s1) {   // resource handles only; identical GPU work is issued on every call
        cudaStreamCreateWithFlags(&g_s1, cudaStreamNonBlocking);
        for (int i = 0; i < 8; i++)
            cudaEventCreateWithFlags(&g_ev[i], cudaEventDisableTiming);
    }
    cudaStream_t D = 0, S = g_s1;

    float *bx0, *bx1, *bagg, *lxA, *lxB, *lagg, *sub, *cntp;
    cudaGetSymbolAddress((void**)&bx0,  g_base_x0);
    cudaGetSymbolAddress((void**)&bx1,  g_base_x1);
    cudaGetSymbolAddress((void**)&bagg, g_base_agg);
    cudaGetSymbolAddress((void**)&lxA,  g_local_x0);
    cudaGetSymbolAddress((void**)&lxB,  g_local_x1);
    cudaGetSymbolAddress((void**)&lagg, g_local_agg);
    cudaGetSymbolAddress((void**)&sub,  g_sub);
    cudaGetSymbolAddress((void**)&cntp, g_cnt);

    int *csr_cnt, *csr_ptr, *csr_fill, *csr_src, *chunks;
    float* csr_w;
    cudaGetSymbolAddress((void**)&csr_cnt,  g_csr_cnt);
    cudaGetSymbolAddress((void**)&csr_ptr,  g_csr_ptr);
    cudaGetSymbolAddress((void**)&csr_fill, g_csr_fill);
    cudaGetSymbolAddress((void**)&csr_src,  g_csr_src);
    cudaGetSymbolAddress((void**)&csr_w,    g_csr_w);
    cudaGetSymbolAddress((void**)&chunks,   g_chunks);

    int*   cnt_b  = csr_cnt;            int*   cnt_l  = csr_cnt + NN;
    int*   ptr_b  = csr_ptr;            int*   ptr_l  = csr_ptr + (NN + 1);
    int*   fill_b = csr_fill;           int*   fill_l = csr_fill + NN;
    int*   src_b  = csr_src;            int*   src_l  = csr_src + EMAX;
    float* w_b    = csr_w;              float* w_l    = csr_w + EMAX;
    int*   chk_b  = chunks;             int*   chk_l  = chunks + 256;

    cudaFuncSetAttribute(gemm128_bias_relu<false>,
                         cudaFuncAttributeMaxDynamicSharedMemorySize, (int)GEMM_SMEM);
    cudaFuncSetAttribute(gemm128_bias_relu<true>,
                         cudaFuncAttributeMaxDynamicSharedMemorySize, (int)GEMM_SMEM);

    const int gb_N = N / 64;
    const int gb_M = M / 64;
    const int eb = (E  + 255) / 256;
    const int el = (EL + 255) / 256;
    const int spmm_blocks_N = (N * 32 + 255) / 256;
    const int spmm_blocks_M = (M * 32 + 255) / 256;

    // ---- fork S from D ----
    cudaEventRecord(g_ev[0], D);
    cudaStreamWaitEvent(S, g_ev[0], 0);

    // ---- S: input projections (FMA-bound) ----
    gemm128_bias_relu<false><<<gb_N, 256, GEMM_SMEM, S>>>(
        x,    Wb, bb, bx0, nullptr, nullptr);
    cudaEventRecord(g_ev[1], S);   // base_x0 ready
    gemm128_bias_relu<false><<<gb_M, 256, GEMM_SMEM, S>>>(
        lx0i, Wl, bl, lxA, nullptr, nullptr);

    // ---- D: CSR build (mem-bound), local graph first ----
    cudaMemsetAsync(csr_cnt,  0, 2 * NN * sizeof(int), D);
    cudaMemsetAsync(csr_fill, 0, 2 * NN * sizeof(int), D);
    hist_kernel<<<el, 256, 0, D>>>(lei + EL, cnt_l, EL);
    chunksum_kernel<<<256, 256, 0, D>>>(cnt_l, chk_l);
    scan_chunks_kernel<<<1, 256, 0, D>>>(chk_l, ptr_l, M);
    write_ptr_kernel<<<256, 256, 0, D>>>(cnt_l, chk_l, ptr_l);
    scatter_kernel<<<el, 256, 0, D>>>(lei, lei + EL, lev, ptr_l, fill_l, src_l, w_l, EL);
    cudaEventRecord(g_ev[2], D);   // local CSR ready
    hist_kernel<<<eb, 256, 0, D>>>(ei + E, cnt_b, E);
    chunksum_kernel<<<256, 256, 0, D>>>(cnt_b, chk_b);
    scan_chunks_kernel<<<1, 256, 0, D>>>(chk_b, ptr_b, N);
    write_ptr_kernel<<<256, 256, 0, D>>>(cnt_b, chk_b, ptr_b);
    scatter_kernel<<<eb, 256, 0, D>>>(ei, ei + E, ew, ptr_b, fill_b, src_b, w_b, E);

    // S needs local CSR before its first spmm
    cudaStreamWaitEvent(S, g_ev[2], 0);
    // D needs base_x0 (from S) before its first spmm
    cudaStreamWaitEvent(D, g_ev[1], 0);

    // ---- layer loop: base chain on D, local chain on S ----
    float* b_in = bx0; float* b_out = bx1;
    float* l_in = lxA; float* l_out = lxB;
    for (int l = 0; l < L; l++) {
        // D: base spmm + gemm
        spmm_csr<<<spmm_blocks_N, 256, 0, D>>>(b_in, ptr_b, src_b, w_b, bagg, N);
        gemm128_bias_relu<false><<<gb_N, 256, GEMM_SMEM, D>>>(
            bagg, Wbase + (size_t)l * HH * HH, bbase + (size_t)l * HH, b_out,
            nullptr, nullptr);
        cudaEventRecord(g_ev[4 + l], D);   // b_out(layer l) ready

        // S: local spmm (overlaps D's gemm), then mix-gemm after b_out ready
        spmm_csr<<<spmm_blocks_M, 256, 0, S>>>(l_in, ptr_l, src_l, w_l, lagg, M);
        cudaStreamWaitEvent(S, g_ev[4 + l], 0);
        gemm128_bias_relu<true><<<gb_M, 256, GEMM_SMEM, S>>>(
            lagg, Wloc + (size_t)l * HH * HH, bloc + (size_t)l * HH, l_out,
            b_out, c2o);

        float* t;
        t = b_in; b_in = b_out; b_out = t;
        t = l_in; l_in = l_out; l_out = t;
    }

    // ---- S: pooling + final projection ----
    cudaMemsetAsync(sub,  0, BB * HH * sizeof(float), S);
    cudaMemsetAsync(cntp, 0, BB * sizeof(float), S);
    const int pool_blocks = 128;
    const int entries_per_block = (K + pool_blocks - 1) / pool_blocks;
    pool_kernel<<<pool_blocks, 256, 0, S>>>(l_in, midx, mgid, sub, cntp, K, entries_per_block);
    final_kernel<<<1, 128, 0, S>>>(sub, cntp, Wp, bp, out);

    // ---- join S back into D ----
    cudaEventRecord(g_ev[7], S);
    cudaStreamWaitEvent(D, g_ev[7], 0);
}